// round 6
// baseline (speedup 1.0000x reference)
#include <cuda_runtime.h>

#define B_SZ 8192
#define K_SZ 25
#define L_SZ 25
#define NTHREADS 128
#define ROWS_PT 8                 // batch rows per thread (four f32x2 pairs)
#define NPAIR 4
#define LSPLIT 4                  // l-range split across blocks: 7,6,6,6
#define LCHUNK 7                  // max l's per block
#define BN_EPS 1e-5f

typedef unsigned long long u64;

__device__ float g_sum[L_SZ];
__device__ float g_sumsq[L_SZ];
__device__ float g_xT[L_SZ * B_SZ];   // raw x, transposed [L][B]

// ---------- packed f32x2 helpers ----------
__device__ __forceinline__ u64 pack2(float a, float b) {
    u64 r;
    asm("mov.b64 %0, {%1, %2};" : "=l"(r) : "r"(__float_as_uint(a)), "r"(__float_as_uint(b)));
    return r;
}
__device__ __forceinline__ u64 dup2(float a) { return pack2(a, a); }
__device__ __forceinline__ float2 unpack2(u64 v) {
    unsigned lo, hi;
    asm("mov.b64 {%0, %1}, %2;" : "=r"(lo), "=r"(hi) : "l"(v));
    return make_float2(__uint_as_float(lo), __uint_as_float(hi));
}
__device__ __forceinline__ u64 ffma2(u64 a, u64 b, u64 c) {
    u64 d;
    asm("fma.rn.f32x2 %0, %1, %2, %3;" : "=l"(d) : "l"(a), "l"(b), "l"(c));
    return d;
}
__device__ __forceinline__ u64 add2(u64 a, u64 b) {
    u64 d;
    asm("add.rn.f32x2 %0, %1, %2;" : "=l"(d) : "l"(a), "l"(b));
    return d;
}
__device__ __forceinline__ u64 relu2(u64 v) {
    float2 f = unpack2(v);
    return pack2(fmaxf(f.x, 0.f), fmaxf(f.y, 0.f));
}

// ---------- kernel 1: fused stats + transpose + out-init (128 blocks x 64 rows) ----------
__global__ void __launch_bounds__(128) prologue_kernel(
    const float* __restrict__ x,
    const float* __restrict__ beta,
    float* __restrict__ out)
{
    __shared__ float t[64][27];
    __shared__ float ps[4][32], pq[4][32];
    __shared__ float sbeta[L_SZ];
    const int tid  = threadIdx.x;
    const int base = blockIdx.x * 64;

    if (tid < L_SZ) sbeta[tid] = beta[tid];
    __syncthreads();

    #pragma unroll
    for (int i = tid; i < 64 * L_SZ; i += 128) {
        int r = i / L_SZ, c = i - r * L_SZ;
        t[r][c] = x[base * L_SZ + i];
        out[base * L_SZ + i] = sbeta[c];
    }
    __syncthreads();

    {
        const int c = tid & 31, g = tid >> 5;
        float s = 0.f, q = 0.f;
        if (c < L_SZ) {
            #pragma unroll
            for (int r = g; r < 64; r += 4) {
                float v = t[r][c];
                s += v;
                q = fmaf(v, v, q);
            }
        }
        ps[g][c] = s;
        pq[g][c] = q;
    }
    __syncthreads();
    if (tid < L_SZ) {
        float S = ps[0][tid] + ps[1][tid] + ps[2][tid] + ps[3][tid];
        float Q = pq[0][tid] + pq[1][tid] + pq[2][tid] + pq[3][tid];
        atomicAdd(&g_sum[tid], S);
        atomicAdd(&g_sumsq[tid], Q);
    }

    #pragma unroll
    for (int i = tid; i < L_SZ * 64; i += 128) {
        int l = i >> 6, r = i & 63;
        g_xT[l * B_SZ + base + r] = t[r][l];
    }
}

// ---------- kernel 2: fused tiny-MLP ensemble, 8 rows/thread ----------
__global__ void __launch_bounds__(NTHREADS, 3) mlp_kernel(
    const float* __restrict__ gamma, const float* __restrict__ bn_bias,
    const float* __restrict__ W1, const float* __restrict__ b1,
    const float* __restrict__ W2, const float* __restrict__ b2,
    const float* __restrict__ W3, const float* __restrict__ b3,
    const float* __restrict__ W4, const float* __restrict__ b4,
    const float* __restrict__ alpha,
    float* __restrict__ out)
{
    __shared__ __align__(16) u64 sW1[LCHUNK][8];
    __shared__ __align__(16) u64 sB1[LCHUNK][8];
    __shared__ __align__(16) u64 sW2[LCHUNK][8][8];
    __shared__ __align__(16) u64 sB2[LCHUNK][8];
    __shared__ __align__(16) u64 sW3[LCHUNK][6][8];
    __shared__ u64 sB3[LCHUNK][6];
    __shared__ __align__(16) u64 sW4[LCHUNK][6];   // pre-scaled by alpha[l,k]
    __shared__ u64 sB4[LCHUNK];                    // pre-scaled by alpha[l,k]
    __shared__ u64 sSc[LCHUNK], sSh[LCHUNK];       // BN scale/shift (dup2)

    const int k      = blockIdx.y;
    const int tid    = threadIdx.x;
    const int z      = blockIdx.z;
    const int lstart = (z == 0) ? 0 : 7 + (z - 1) * 6;
    const int nl     = (z == 0) ? 7 : 6;

    {
        const float* p = W1 + (k * L_SZ + lstart) * 8;
        for (int i = tid; i < nl * 8; i += NTHREADS) ((u64*)sW1)[i] = dup2(p[i]);
        p = b1 + (k * L_SZ + lstart) * 8;
        for (int i = tid; i < nl * 8; i += NTHREADS) ((u64*)sB1)[i] = dup2(p[i]);
        p = W2 + (k * L_SZ + lstart) * 64;
        for (int i = tid; i < nl * 64; i += NTHREADS) ((u64*)sW2)[i] = dup2(p[i]);
        p = b2 + (k * L_SZ + lstart) * 8;
        for (int i = tid; i < nl * 8; i += NTHREADS) ((u64*)sB2)[i] = dup2(p[i]);
        p = W3 + (k * L_SZ + lstart) * 48;
        for (int i = tid; i < nl * 48; i += NTHREADS) ((u64*)sW3)[i] = dup2(p[i]);
        p = b3 + (k * L_SZ + lstart) * 6;
        for (int i = tid; i < nl * 6; i += NTHREADS) ((u64*)sB3)[i] = dup2(p[i]);
        p = W4 + (k * L_SZ + lstart) * 6;
        for (int i = tid; i < nl * 6; i += NTHREADS) {
            int gl = lstart + i / 6;
            ((u64*)sW4)[i] = dup2(p[i] * alpha[gl * K_SZ + k]);
        }
        for (int i = tid; i < nl; i += NTHREADS) {
            int gl = lstart + i;
            sB4[i] = dup2(b4[k * L_SZ + gl] * alpha[gl * K_SZ + k]);
            float mean = g_sum[gl] * (1.f / (float)B_SZ);
            float var  = g_sumsq[gl] * (1.f / (float)B_SZ) - mean * mean;
            float s    = gamma[gl] * rsqrtf(var + BN_EPS);
            sSc[i] = dup2(s);
            sSh[i] = dup2(bn_bias[gl] - mean * s);
        }
    }
    __syncthreads();

    const int b0 = (blockIdx.x * NTHREADS + tid) * ROWS_PT;
    u64 acc[NPAIR] = {0ULL, 0ULL, 0ULL, 0ULL};

    // software-pipelined x loads (two LDG.128 per l)
    ulonglong2 xva = *(const ulonglong2*)(g_xT + lstart * B_SZ + b0);
    ulonglong2 xvb = *(const ulonglong2*)(g_xT + lstart * B_SZ + b0 + 4);

    #pragma unroll 1
    for (int li = 0; li < nl; ++li) {
        ulonglong2 xna, xnb;
        if (li + 1 < nl) {
            xna = *(const ulonglong2*)(g_xT + (lstart + li + 1) * B_SZ + b0);
            xnb = *(const ulonglong2*)(g_xT + (lstart + li + 1) * B_SZ + b0 + 4);
        }
        u64 scl = sSc[li], shl = sSh[li];
        u64 xn[NPAIR];
        xn[0] = ffma2(xva.x, scl, shl);
        xn[1] = ffma2(xva.y, scl, shl);
        xn[2] = ffma2(xvb.x, scl, shl);
        xn[3] = ffma2(xvb.y, scl, shl);

        // layer 1: 1 -> 8
        u64 h1[NPAIR][8];
        {
            const ulonglong2* w  = (const ulonglong2*)sW1[li];
            const ulonglong2* bb = (const ulonglong2*)sB1[li];
            #pragma unroll
            for (int t = 0; t < 4; ++t) {
                ulonglong2 wv = w[t], bv = bb[t];
                #pragma unroll
                for (int p = 0; p < NPAIR; ++p) {
                    h1[p][2*t]   = relu2(ffma2(xn[p], wv.x, bv.x));
                    h1[p][2*t+1] = relu2(ffma2(xn[p], wv.y, bv.y));
                }
            }
        }

        // layer 2: 8 -> 8
        u64 h2[NPAIR][8];
        #pragma unroll
        for (int i = 0; i < 8; ++i) {
            const ulonglong2* w = (const ulonglong2*)sW2[li][i];
            ulonglong2 w0 = w[0], w1 = w[1], w2 = w[2], w3 = w[3];
            u64 wj[8] = {w0.x, w0.y, w1.x, w1.y, w2.x, w2.y, w3.x, w3.y};
            u64 bi = sB2[li][i];
            u64 a[NPAIR] = {bi, bi, bi, bi};
            #pragma unroll
            for (int j = 0; j < 8; ++j)
                #pragma unroll
                for (int p = 0; p < NPAIR; ++p)
                    a[p] = ffma2(h1[p][j], wj[j], a[p]);
            #pragma unroll
            for (int p = 0; p < NPAIR; ++p) h2[p][i] = relu2(a[p]);
        }

        // layer 3: 8 -> 6
        u64 h3[NPAIR][6];
        #pragma unroll
        for (int i = 0; i < 6; ++i) {
            const ulonglong2* w = (const ulonglong2*)sW3[li][i];
            ulonglong2 w0 = w[0], w1 = w[1], w2 = w[2], w3 = w[3];
            u64 wj[8] = {w0.x, w0.y, w1.x, w1.y, w2.x, w2.y, w3.x, w3.y};
            u64 bi = sB3[li][i];
            u64 a[NPAIR] = {bi, bi, bi, bi};
            #pragma unroll
            for (int j = 0; j < 8; ++j)
                #pragma unroll
                for (int p = 0; p < NPAIR; ++p)
                    a[p] = ffma2(h2[p][j], wj[j], a[p]);
            #pragma unroll
            for (int p = 0; p < NPAIR; ++p) h3[p][i] = relu2(a[p]);
        }

        // layer 4 (alpha pre-folded)
        {
            const ulonglong2* w = (const ulonglong2*)sW4[li];
            ulonglong2 w0 = w[0], w1 = w[1], w2 = w[2];
            u64 wj[6] = {w0.x, w0.y, w1.x, w1.y, w2.x, w2.y};
            u64 bi = sB4[li];
            u64 f[NPAIR] = {bi, bi, bi, bi};
            #pragma unroll
            for (int j = 0; j < 6; ++j)
                #pragma unroll
                for (int p = 0; p < NPAIR; ++p)
                    f[p] = ffma2(h3[p][j], wj[j], f[p]);
            #pragma unroll
            for (int p = 0; p < NPAIR; ++p) acc[p] = add2(acc[p], f[p]);
        }
        xva = xna;
        xvb = xnb;
    }

    #pragma unroll
    for (int p = 0; p < NPAIR; ++p) {
        float2 r = unpack2(acc[p]);
        atomicAdd(out + (b0 + 2*p + 0) * K_SZ + k, r.x);
        atomicAdd(out + (b0 + 2*p + 1) * K_SZ + k, r.y);
    }
}

extern "C" void kernel_launch(void* const* d_in, const int* in_sizes, int n_in,
                              void* d_out, int out_size) {
    const float* x      = (const float*)d_in[0];
    const float* gamma  = (const float*)d_in[1];
    const float* bnb    = (const float*)d_in[2];
    const float* W1     = (const float*)d_in[3];
    const float* b1     = (const float*)d_in[4];
    const float* W2     = (const float*)d_in[5];
    const float* b2     = (const float*)d_in[6];
    const float* W3     = (const float*)d_in[7];
    const float* b3     = (const float*)d_in[8];
    const float* W4     = (const float*)d_in[9];
    const float* b4     = (const float*)d_in[10];
    const float* alpha  = (const float*)d_in[11];
    const float* beta   = (const float*)d_in[12];
    float* out = (float*)d_out;

    void* p_sum = nullptr;
    void* p_sq  = nullptr;
    cudaGetSymbolAddress(&p_sum, g_sum);
    cudaGetSymbolAddress(&p_sq,  g_sumsq);
    cudaMemsetAsync(p_sum, 0, L_SZ * sizeof(float));
    cudaMemsetAsync(p_sq,  0, L_SZ * sizeof(float));

    prologue_kernel<<<B_SZ / 64, 128>>>(x, beta, out);
    mlp_kernel<<<dim3(B_SZ / (ROWS_PT * NTHREADS), K_SZ, LSPLIT), NTHREADS>>>(
        gamma, bnb, W1, b1, W2, b2, W3, b3, W4, b4, alpha, out);
}

// round 7
// speedup vs baseline: 1.0164x; 1.0164x over previous
#include <cuda_runtime.h>

#define B_SZ 8192
#define K_SZ 25
#define L_SZ 25
#define NTHREADS 128
#define ROWS_PT 8                 // batch rows per thread (four f32x2 pairs)
#define NPAIR 4
#define LSPLIT 8                  // l-chunks: 4,3,3,3,3,3,3,3
#define LCHUNK 4
#define BN_EPS 1e-5f

typedef unsigned long long u64;

__device__ float g_sum[L_SZ];
__device__ float g_sumsq[L_SZ];
__device__ float g_xT[L_SZ * B_SZ];   // raw x, transposed [L][B]

// ---------- packed f32x2 helpers ----------
__device__ __forceinline__ u64 pack2(float a, float b) {
    u64 r;
    asm("mov.b64 %0, {%1, %2};" : "=l"(r) : "r"(__float_as_uint(a)), "r"(__float_as_uint(b)));
    return r;
}
__device__ __forceinline__ u64 dup2(float a) { return pack2(a, a); }
__device__ __forceinline__ float2 unpack2(u64 v) {
    unsigned lo, hi;
    asm("mov.b64 {%0, %1}, %2;" : "=r"(lo), "=r"(hi) : "l"(v));
    return make_float2(__uint_as_float(lo), __uint_as_float(hi));
}
__device__ __forceinline__ u64 ffma2(u64 a, u64 b, u64 c) {
    u64 d;
    asm("fma.rn.f32x2 %0, %1, %2, %3;" : "=l"(d) : "l"(a), "l"(b), "l"(c));
    return d;
}
__device__ __forceinline__ u64 add2(u64 a, u64 b) {
    u64 d;
    asm("add.rn.f32x2 %0, %1, %2;" : "=l"(d) : "l"(a), "l"(b));
    return d;
}
__device__ __forceinline__ u64 relu2(u64 v) {
    float2 f = unpack2(v);
    return pack2(fmaxf(f.x, 0.f), fmaxf(f.y, 0.f));
}

// ---------- kernel 1: fused stats + transpose + out-init ----------
__global__ void __launch_bounds__(128) prologue_kernel(
    const float* __restrict__ x,
    const float* __restrict__ beta,
    float* __restrict__ out)
{
    __shared__ float t[64][27];
    __shared__ float ps[4][32], pq[4][32];
    __shared__ float sbeta[L_SZ];
    const int tid  = threadIdx.x;
    const int base = blockIdx.x * 64;

    if (tid < L_SZ) sbeta[tid] = beta[tid];
    __syncthreads();

    #pragma unroll
    for (int i = tid; i < 64 * L_SZ; i += 128) {
        int r = i / L_SZ, c = i - r * L_SZ;
        t[r][c] = x[base * L_SZ + i];
        out[base * L_SZ + i] = sbeta[c];
    }
    __syncthreads();

    {
        const int c = tid & 31, g = tid >> 5;
        float s = 0.f, q = 0.f;
        if (c < L_SZ) {
            #pragma unroll
            for (int r = g; r < 64; r += 4) {
                float v = t[r][c];
                s += v;
                q = fmaf(v, v, q);
            }
        }
        ps[g][c] = s;
        pq[g][c] = q;
    }
    __syncthreads();
    if (tid < L_SZ) {
        float S = ps[0][tid] + ps[1][tid] + ps[2][tid] + ps[3][tid];
        float Q = pq[0][tid] + pq[1][tid] + pq[2][tid] + pq[3][tid];
        atomicAdd(&g_sum[tid], S);
        atomicAdd(&g_sumsq[tid], Q);
    }

    #pragma unroll
    for (int i = tid; i < L_SZ * 64; i += 128) {
        int l = i >> 6, r = i & 63;
        g_xT[l * B_SZ + base + r] = t[r][l];
    }
}

// ---------- kernel 2: fused tiny-MLP ensemble, 8 rows/thread, 4 blk/SM ----------
__global__ void __launch_bounds__(NTHREADS, 4) mlp_kernel(
    const float* __restrict__ gamma, const float* __restrict__ bn_bias,
    const float* __restrict__ W1, const float* __restrict__ b1,
    const float* __restrict__ W2, const float* __restrict__ b2,
    const float* __restrict__ W3, const float* __restrict__ b3,
    const float* __restrict__ W4, const float* __restrict__ b4,
    const float* __restrict__ alpha,
    float* __restrict__ out)
{
    // BN folded into W1/b1; alpha folded into W4/b4
    __shared__ __align__(16) u64 sW1[LCHUNK][8];
    __shared__ __align__(16) u64 sB1[LCHUNK][8];
    __shared__ __align__(16) u64 sW2[LCHUNK][8][8];
    __shared__ __align__(16) u64 sB2[LCHUNK][8];
    __shared__ __align__(16) u64 sW3[LCHUNK][6][8];
    __shared__ u64 sB3[LCHUNK][6];
    __shared__ __align__(16) u64 sW4[LCHUNK][6];
    __shared__ u64 sB4[LCHUNK];

    const int k      = blockIdx.y;
    const int tid    = threadIdx.x;
    const int z      = blockIdx.z;
    const int lstart = (z == 0) ? 0 : 4 + (z - 1) * 3;
    const int nl     = (z == 0) ? 4 : 3;

    {
        // layer-1 fill with BN fold: W1' = W1*sc, b1' = b1 + W1*sh
        const float* pw = W1 + (k * L_SZ + lstart) * 8;
        const float* pb = b1 + (k * L_SZ + lstart) * 8;
        for (int i = tid; i < nl * 8; i += NTHREADS) {
            int gl = lstart + (i >> 3);
            float mean = g_sum[gl] * (1.f / (float)B_SZ);
            float var  = g_sumsq[gl] * (1.f / (float)B_SZ) - mean * mean;
            float sc   = gamma[gl] * rsqrtf(var + BN_EPS);
            float sh   = bn_bias[gl] - mean * sc;
            float w    = pw[i];
            ((u64*)sW1)[i] = dup2(w * sc);
            ((u64*)sB1)[i] = dup2(fmaf(w, sh, pb[i]));
        }
        const float* p = W2 + (k * L_SZ + lstart) * 64;
        for (int i = tid; i < nl * 64; i += NTHREADS) ((u64*)sW2)[i] = dup2(p[i]);
        p = b2 + (k * L_SZ + lstart) * 8;
        for (int i = tid; i < nl * 8; i += NTHREADS) ((u64*)sB2)[i] = dup2(p[i]);
        p = W3 + (k * L_SZ + lstart) * 48;
        for (int i = tid; i < nl * 48; i += NTHREADS) ((u64*)sW3)[i] = dup2(p[i]);
        p = b3 + (k * L_SZ + lstart) * 6;
        for (int i = tid; i < nl * 6; i += NTHREADS) ((u64*)sB3)[i] = dup2(p[i]);
        p = W4 + (k * L_SZ + lstart) * 6;
        for (int i = tid; i < nl * 6; i += NTHREADS) {
            int gl = lstart + i / 6;
            ((u64*)sW4)[i] = dup2(p[i] * alpha[gl * K_SZ + k]);
        }
        for (int i = tid; i < nl; i += NTHREADS) {
            int gl = lstart + i;
            sB4[i] = dup2(b4[k * L_SZ + gl] * alpha[gl * K_SZ + k]);
        }
    }
    __syncthreads();

    const int b0 = (blockIdx.x * NTHREADS + tid) * ROWS_PT;
    u64 acc[NPAIR] = {0ULL, 0ULL, 0ULL, 0ULL};

    #pragma unroll 1
    for (int li = 0; li < nl; ++li) {
        // x loaded at loop top; latency hidden by co-resident warps
        ulonglong2 xva = *(const ulonglong2*)(g_xT + (lstart + li) * B_SZ + b0);
        ulonglong2 xvb = *(const ulonglong2*)(g_xT + (lstart + li) * B_SZ + b0 + 4);
        u64 xn[NPAIR] = {xva.x, xva.y, xvb.x, xvb.y};

        // layer 1: 1 -> 8 (BN pre-folded into weights)
        u64 h1[NPAIR][8];
        {
            const ulonglong2* w  = (const ulonglong2*)sW1[li];
            const ulonglong2* bb = (const ulonglong2*)sB1[li];
            #pragma unroll
            for (int t = 0; t < 4; ++t) {
                ulonglong2 wv = w[t], bv = bb[t];
                #pragma unroll
                for (int p = 0; p < NPAIR; ++p) {
                    h1[p][2*t]   = relu2(ffma2(xn[p], wv.x, bv.x));
                    h1[p][2*t+1] = relu2(ffma2(xn[p], wv.y, bv.y));
                }
            }
        }

        // layer 2: 8 -> 8
        u64 h2[NPAIR][8];
        #pragma unroll
        for (int i = 0; i < 8; ++i) {
            const ulonglong2* w = (const ulonglong2*)sW2[li][i];
            ulonglong2 w0 = w[0], w1 = w[1], w2 = w[2], w3 = w[3];
            u64 wj[8] = {w0.x, w0.y, w1.x, w1.y, w2.x, w2.y, w3.x, w3.y};
            u64 bi = sB2[li][i];
            u64 a[NPAIR] = {bi, bi, bi, bi};
            #pragma unroll
            for (int j = 0; j < 8; ++j)
                #pragma unroll
                for (int p = 0; p < NPAIR; ++p)
                    a[p] = ffma2(h1[p][j], wj[j], a[p]);
            #pragma unroll
            for (int p = 0; p < NPAIR; ++p) h2[p][i] = relu2(a[p]);
        }

        // layer 3: 8 -> 6
        u64 h3[NPAIR][6];
        #pragma unroll
        for (int i = 0; i < 6; ++i) {
            const ulonglong2* w = (const ulonglong2*)sW3[li][i];
            ulonglong2 w0 = w[0], w1 = w[1], w2 = w[2], w3 = w[3];
            u64 wj[8] = {w0.x, w0.y, w1.x, w1.y, w2.x, w2.y, w3.x, w3.y};
            u64 bi = sB3[li][i];
            u64 a[NPAIR] = {bi, bi, bi, bi};
            #pragma unroll
            for (int j = 0; j < 8; ++j)
                #pragma unroll
                for (int p = 0; p < NPAIR; ++p)
                    a[p] = ffma2(h2[p][j], wj[j], a[p]);
            #pragma unroll
            for (int p = 0; p < NPAIR; ++p) h3[p][i] = relu2(a[p]);
        }

        // layer 4 (alpha pre-folded)
        {
            const ulonglong2* w = (const ulonglong2*)sW4[li];
            ulonglong2 w0 = w[0], w1 = w[1], w2 = w[2];
            u64 wj[6] = {w0.x, w0.y, w1.x, w1.y, w2.x, w2.y};
            u64 bi = sB4[li];
            u64 f[NPAIR] = {bi, bi, bi, bi};
            #pragma unroll
            for (int j = 0; j < 6; ++j)
                #pragma unroll
                for (int p = 0; p < NPAIR; ++p)
                    f[p] = ffma2(h3[p][j], wj[j], f[p]);
            #pragma unroll
            for (int p = 0; p < NPAIR; ++p) acc[p] = add2(acc[p], f[p]);
        }
    }

    #pragma unroll
    for (int p = 0; p < NPAIR; ++p) {
        float2 r = unpack2(acc[p]);
        atomicAdd(out + (b0 + 2*p + 0) * K_SZ + k, r.x);
        atomicAdd(out + (b0 + 2*p + 1) * K_SZ + k, r.y);
    }
}

extern "C" void kernel_launch(void* const* d_in, const int* in_sizes, int n_in,
                              void* d_out, int out_size) {
    const float* x      = (const float*)d_in[0];
    const float* gamma  = (const float*)d_in[1];
    const float* bnb    = (const float*)d_in[2];
    const float* W1     = (const float*)d_in[3];
    const float* b1     = (const float*)d_in[4];
    const float* W2     = (const float*)d_in[5];
    const float* b2     = (const float*)d_in[6];
    const float* W3     = (const float*)d_in[7];
    const float* b3     = (const float*)d_in[8];
    const float* W4     = (const float*)d_in[9];
    const float* b4     = (const float*)d_in[10];
    const float* alpha  = (const float*)d_in[11];
    const float* beta   = (const float*)d_in[12];
    float* out = (float*)d_out;

    void* p_sum = nullptr;
    void* p_sq  = nullptr;
    cudaGetSymbolAddress(&p_sum, g_sum);
    cudaGetSymbolAddress(&p_sq,  g_sumsq);
    cudaMemsetAsync(p_sum, 0, L_SZ * sizeof(float));
    cudaMemsetAsync(p_sq,  0, L_SZ * sizeof(float));

    prologue_kernel<<<B_SZ / 64, 128>>>(x, beta, out);
    mlp_kernel<<<dim3(B_SZ / (ROWS_PT * NTHREADS), K_SZ, LSPLIT), NTHREADS>>>(
        gamma, bnb, W1, b1, W2, b2, W3, b3, W4, b4, alpha, out);
}